// round 16
// baseline (speedup 1.0000x reference)
#include <cuda_runtime.h>
#include <cuda_bf16.h>

#define FEAT 64
#define EPR 136             // edges per 16-lane group -> 736 blocks
                            // (near-perfect 5 CTAs/SM single wave; 136%4==0,
                            //  row*136*4B is 16B-aligned for int4/float4 loads)
#define ROWS_PER_BLOCK 16   // 256 threads / 16 lanes
#define THREADS 256

// K0: zero exactly the nodes that receive atomicAdd flushes — nodes whose
// segment crosses a chunk boundary (seg[b*EPR-1] == seg[b*EPR]).
// Re-runs every call -> graph-replay idempotent.
__global__ void __launch_bounds__(THREADS)
zero_boundary_kernel(const int* __restrict__ seg,
                     float4* __restrict__ out4,   // [N*16]
                     int n_rows, int n_edges) {
    int b    = blockIdx.x * ROWS_PER_BLOCK + (threadIdx.x >> 4) + 1;
    int lane = threadIdx.x & 15;
    if (b >= n_rows) return;
    int e = b * EPR;
    if (e >= n_edges) return;
    int s = __ldg(&seg[e]);
    if (__ldg(&seg[e - 1]) == s)
        out4[(size_t)s * 16 + lane] = make_float4(0.f, 0.f, 0.f, 0.f);
}

// K1: weighted segment-sum over sorted segment_ids (R13 loop with packed
// seg/attn loads: one int4 + one float4 LDG per 4-edge batch instead of 8
// scalar LDGs -> halves LSU dispatch slots in the hot loop).
// 16-lane groups own EPR-edge chunks; lane l owns features [4l,4l+4).
// Runs contained in one chunk -> single plain STG.128 of acc+bias (sole
// writer, idempotent). Boundary-crossing segments -> atomicAdd onto the
// K0-zeroed node; the segment's START owner adds bias exactly once.
__global__ void __launch_bounds__(THREADS)
segsum_kernel(const float4* __restrict__ feats,   // [E,16] float4 view of [E,64]
              const float4* __restrict__ attn4,   // [E/4] packed attention
              const int4*   __restrict__ seg4,    // [E/4] packed segment ids
              const int*    __restrict__ seg,     // [E] scalar view
              float* __restrict__ out,            // [N,64]
              const float4* __restrict__ bias4,   // [16]
              int n_edges, int n_nodes) {
    int row  = blockIdx.x * ROWS_PER_BLOCK + (threadIdx.x >> 4);
    int lane = threadIdx.x & 15;

    int e0 = row * EPR;
    if (e0 >= n_edges) return;
    int e_end = e0 + EPR;
    if (e_end > n_edges) e_end = n_edges;

    float4 bia = __ldg(&bias4[lane]);
    float4 acc = make_float4(0.f, 0.f, 0.f, 0.f);
    int  cur   = __ldg(&seg[e0]);
    bool first = true;   // still inside the chunk's first run
    bool owned_head = (e0 == 0) || (__ldg(&seg[e0 - 1]) != cur);

    // leading empty nodes [0, seg[0]) — only the very first group
    if (e0 == 0) {
        for (int m = 0; m < cur; ++m)
            ((float4*)(out + (size_t)m * FEAT))[lane] = bia;
    }

    #define STEP(S, A, F)                                                      \
    do {                                                                       \
        if (S != cur) {                                                        \
            if (first && !owned_head) {                                        \
                /* continuation of a segment started earlier: raw partial */   \
                float* o = out + (size_t)cur * FEAT + lane * 4;                \
                atomicAdd(o + 0, acc.x); atomicAdd(o + 1, acc.y);              \
                atomicAdd(o + 2, acc.z); atomicAdd(o + 3, acc.w);              \
            } else {                                                           \
                /* run started and ended here: sole writer, bias fused */      \
                float4 v = make_float4(acc.x + bia.x, acc.y + bia.y,           \
                                       acc.z + bia.z, acc.w + bia.w);          \
                ((float4*)(out + (size_t)cur * FEAT))[lane] = v;               \
            }                                                                  \
            for (int m = cur + 1; m < S; ++m)                                  \
                ((float4*)(out + (size_t)m * FEAT))[lane] = bia;               \
            first = false;                                                     \
            acc = make_float4(0.f, 0.f, 0.f, 0.f);                             \
            cur = S;                                                           \
        }                                                                      \
        acc.x = fmaf(A, F.x, acc.x); acc.y = fmaf(A, F.y, acc.y);              \
        acc.z = fmaf(A, F.z, acc.z); acc.w = fmaf(A, F.w, acc.w);              \
    } while (0)

    int e = e0;
    for (; e + 4 <= e_end; e += 4) {
        // ---- load phase: 6 independent LDGs (1 seg4 + 1 attn4 + 4 feat) ----
        int4   sv = __ldg(&seg4[e >> 2]);
        float4 av = __ldg(&attn4[e >> 2]);
        float4 f0 = __ldg(&feats[(size_t)(e + 0) * 16 + lane]);
        float4 f1 = __ldg(&feats[(size_t)(e + 1) * 16 + lane]);
        float4 f2 = __ldg(&feats[(size_t)(e + 2) * 16 + lane]);
        float4 f3 = __ldg(&feats[(size_t)(e + 3) * 16 + lane]);

        // ---- process phase ----
        STEP(sv.x, av.x, f0);
        STEP(sv.y, av.y, f1);
        STEP(sv.z, av.z, f2);
        STEP(sv.w, av.w, f3);
    }
    for (; e < e_end; ++e) {
        int   s = __ldg(&seg[e]);
        float a = ((const float*)attn4)[e];
        float4 f = __ldg(&feats[(size_t)e * 16 + lane]);
        STEP(s, a, f);
    }
    #undef STEP

    // tail flush
    bool has_next = (e_end < n_edges);
    int  next_s   = has_next ? __ldg(&seg[e_end]) : n_nodes;
    bool tail_shared = has_next && (next_s == cur);

    if (first && !owned_head) {
        // whole chunk sits inside a larger segment: raw continuation partial
        float* o = out + (size_t)cur * FEAT + lane * 4;
        atomicAdd(o + 0, acc.x); atomicAdd(o + 1, acc.y);
        atomicAdd(o + 2, acc.z); atomicAdd(o + 3, acc.w);
    } else if (tail_shared) {
        // segment STARTS here and crosses out: owner contributes bias once
        float* o = out + (size_t)cur * FEAT + lane * 4;
        atomicAdd(o + 0, acc.x + bia.x); atomicAdd(o + 1, acc.y + bia.y);
        atomicAdd(o + 2, acc.z + bia.z); atomicAdd(o + 3, acc.w + bia.w);
    } else {
        // segment starts and ends within this chunk: sole writer
        float4 v = make_float4(acc.x + bia.x, acc.y + bia.y,
                               acc.z + bia.z, acc.w + bia.w);
        ((float4*)(out + (size_t)cur * FEAT))[lane] = v;
    }

    // trailing empty nodes up to the next chunk's first segment (or N)
    for (int m = cur + 1; m < next_s; ++m)
        ((float4*)(out + (size_t)m * FEAT))[lane] = bia;
}

extern "C" void kernel_launch(void* const* d_in, const int* in_sizes, int n_in,
                              void* d_out, int out_size) {
    // metadata order: nodes[0] (unused), neighbor_feats[1], attention[2],
    //                 bias[3], segment_ids[4]
    const float* feats = (const float*)d_in[1];
    const float* attn  = (const float*)d_in[2];
    const float* bias  = (const float*)d_in[3];
    const int*   seg   = (const int*)d_in[4];
    float* out = (float*)d_out;

    int n_edges = in_sizes[2];          // attention element count = E
    int n_nodes = out_size / FEAT;      // N
    int n_rows  = (n_edges + EPR - 1) / EPR;
    int blocks  = (n_rows + ROWS_PER_BLOCK - 1) / ROWS_PER_BLOCK;

    // K0: zero future atomic targets (boundary-crossing nodes only)
    zero_boundary_kernel<<<blocks, THREADS>>>(seg, (float4*)out,
                                              n_rows, n_edges);

    // K1: front-batched single-pass weighted segment-sum, packed id/attn loads
    segsum_kernel<<<blocks, THREADS>>>((const float4*)feats,
                                       (const float4*)attn,
                                       (const int4*)seg, seg, out,
                                       (const float4*)bias,
                                       n_edges, n_nodes);
}

// round 17
// speedup vs baseline: 1.0275x; 1.0275x over previous
#include <cuda_runtime.h>
#include <cuda_bf16.h>

#define FEAT 64
#define EPR 136             // edges per 16-lane group -> 736 blocks
                            // = near-perfect 5 CTAs/SM single wave (cap 740)
#define ROWS_PER_BLOCK 16   // 256 threads / 16 lanes
#define THREADS 256

// K0: zero exactly the nodes that receive atomicAdd flushes — nodes whose
// segment crosses a chunk boundary (seg[b*EPR-1] == seg[b*EPR]).
// Re-runs every call -> graph-replay idempotent. Triggers PDL at entry so
// K1's launch ramp overlaps this kernel's execution.
__global__ void __launch_bounds__(THREADS)
zero_boundary_kernel(const int* __restrict__ seg,
                     float4* __restrict__ out4,   // [N*16]
                     int n_rows, int n_edges) {
#if __CUDA_ARCH__ >= 900
    cudaTriggerProgrammaticLaunchCompletion();
#endif
    int b    = blockIdx.x * ROWS_PER_BLOCK + (threadIdx.x >> 4) + 1;
    int lane = threadIdx.x & 15;
    if (b >= n_rows) return;
    int e = b * EPR;
    if (e >= n_edges) return;
    int s = __ldg(&seg[e]);
    if (__ldg(&seg[e - 1]) == s)
        out4[(size_t)s * 16 + lane] = make_float4(0.f, 0.f, 0.f, 0.f);
}

// K1: weighted segment-sum over sorted segment_ids (R13-exact hot loop).
// Launched with programmatic stream serialization: CTAs spin up during K0 and
// block on cudaGridDependencySynchronize() before their first store/atomic.
__global__ void __launch_bounds__(THREADS)
segsum_kernel(const float4* __restrict__ feats,   // [E,16] float4 view of [E,64]
              const float*  __restrict__ attn,    // [E]
              const int*    __restrict__ seg,     // [E] sorted
              float* __restrict__ out,            // [N,64]
              const float4* __restrict__ bias4,   // [16]
              int n_edges, int n_nodes) {
    int row  = blockIdx.x * ROWS_PER_BLOCK + (threadIdx.x >> 4);
    int lane = threadIdx.x & 15;

    int e0 = row * EPR;
    if (e0 >= n_edges) {
#if __CUDA_ARCH__ >= 900
        cudaGridDependencySynchronize();
#endif
        return;
    }
    int e_end = e0 + EPR;
    if (e_end > n_edges) e_end = n_edges;

    // preamble loads (independent of K0's writes to out)
    float4 bia = __ldg(&bias4[lane]);
    float4 acc = make_float4(0.f, 0.f, 0.f, 0.f);
    int  cur   = __ldg(&seg[e0]);
    bool first = true;   // still inside the chunk's first run
    bool owned_head = (e0 == 0) || (__ldg(&seg[e0 - 1]) != cur);

    // K0 must be fully visible before any store/atomic to `out`
#if __CUDA_ARCH__ >= 900
    cudaGridDependencySynchronize();
#endif

    // leading empty nodes [0, seg[0]) — only the very first group
    if (e0 == 0) {
        for (int m = 0; m < cur; ++m)
            ((float4*)(out + (size_t)m * FEAT))[lane] = bia;
    }

    #define STEP(S, A, F)                                                      \
    do {                                                                       \
        if (S != cur) {                                                        \
            if (first && !owned_head) {                                        \
                /* continuation of a segment started earlier: raw partial */   \
                float* o = out + (size_t)cur * FEAT + lane * 4;                \
                atomicAdd(o + 0, acc.x); atomicAdd(o + 1, acc.y);              \
                atomicAdd(o + 2, acc.z); atomicAdd(o + 3, acc.w);              \
            } else {                                                           \
                /* run started and ended here: sole writer, bias fused */      \
                float4 v = make_float4(acc.x + bia.x, acc.y + bia.y,           \
                                       acc.z + bia.z, acc.w + bia.w);          \
                ((float4*)(out + (size_t)cur * FEAT))[lane] = v;               \
            }                                                                  \
            for (int m = cur + 1; m < S; ++m)                                  \
                ((float4*)(out + (size_t)m * FEAT))[lane] = bia;               \
            first = false;                                                     \
            acc = make_float4(0.f, 0.f, 0.f, 0.f);                             \
            cur = S;                                                           \
        }                                                                      \
        acc.x = fmaf(A, F.x, acc.x); acc.y = fmaf(A, F.y, acc.y);              \
        acc.z = fmaf(A, F.z, acc.z); acc.w = fmaf(A, F.w, acc.w);              \
    } while (0)

    int e = e0;
    for (; e + 4 <= e_end; e += 4) {
        // ---- load phase: independent LDGs, no control flow between them ----
        int   s0 = __ldg(&seg[e + 0]), s1 = __ldg(&seg[e + 1]);
        int   s2 = __ldg(&seg[e + 2]), s3 = __ldg(&seg[e + 3]);
        float a0 = __ldg(&attn[e + 0]), a1 = __ldg(&attn[e + 1]);
        float a2 = __ldg(&attn[e + 2]), a3 = __ldg(&attn[e + 3]);
        float4 f0 = __ldg(&feats[(size_t)(e + 0) * 16 + lane]);
        float4 f1 = __ldg(&feats[(size_t)(e + 1) * 16 + lane]);
        float4 f2 = __ldg(&feats[(size_t)(e + 2) * 16 + lane]);
        float4 f3 = __ldg(&feats[(size_t)(e + 3) * 16 + lane]);

        // ---- process phase ----
        STEP(s0, a0, f0);
        STEP(s1, a1, f1);
        STEP(s2, a2, f2);
        STEP(s3, a3, f3);
    }
    for (; e < e_end; ++e) {
        int   s = __ldg(&seg[e]);
        float a = __ldg(&attn[e]);
        float4 f = __ldg(&feats[(size_t)e * 16 + lane]);
        STEP(s, a, f);
    }
    #undef STEP

    // tail flush
    bool has_next = (e_end < n_edges);
    int  next_s   = has_next ? __ldg(&seg[e_end]) : n_nodes;
    bool tail_shared = has_next && (next_s == cur);

    if (first && !owned_head) {
        // whole chunk sits inside a larger segment: raw continuation partial
        float* o = out + (size_t)cur * FEAT + lane * 4;
        atomicAdd(o + 0, acc.x); atomicAdd(o + 1, acc.y);
        atomicAdd(o + 2, acc.z); atomicAdd(o + 3, acc.w);
    } else if (tail_shared) {
        // segment STARTS here and crosses out: owner contributes bias once
        float* o = out + (size_t)cur * FEAT + lane * 4;
        atomicAdd(o + 0, acc.x + bia.x); atomicAdd(o + 1, acc.y + bia.y);
        atomicAdd(o + 2, acc.z + bia.z); atomicAdd(o + 3, acc.w + bia.w);
    } else {
        // segment starts and ends within this chunk: sole writer
        float4 v = make_float4(acc.x + bia.x, acc.y + bia.y,
                               acc.z + bia.z, acc.w + bia.w);
        ((float4*)(out + (size_t)cur * FEAT))[lane] = v;
    }

    // trailing empty nodes up to the next chunk's first segment (or N)
    for (int m = cur + 1; m < next_s; ++m)
        ((float4*)(out + (size_t)m * FEAT))[lane] = bia;
}

extern "C" void kernel_launch(void* const* d_in, const int* in_sizes, int n_in,
                              void* d_out, int out_size) {
    // metadata order: nodes[0] (unused), neighbor_feats[1], attention[2],
    //                 bias[3], segment_ids[4]
    const float* feats = (const float*)d_in[1];
    const float* attn  = (const float*)d_in[2];
    const float* bias  = (const float*)d_in[3];
    const int*   seg   = (const int*)d_in[4];
    float* out = (float*)d_out;

    int n_edges = in_sizes[2];          // attention element count = E
    int n_nodes = out_size / FEAT;      // N
    int n_rows  = (n_edges + EPR - 1) / EPR;
    int blocks  = (n_rows + ROWS_PER_BLOCK - 1) / ROWS_PER_BLOCK;

    // K0: zero future atomic targets (boundary-crossing nodes only)
    zero_boundary_kernel<<<blocks, THREADS>>>(seg, (float4*)out,
                                              n_rows, n_edges);

    // K1: R13 segsum, launched with PDL so its ramp overlaps K0
    {
        cudaLaunchConfig_t cfg = {};
        cfg.gridDim  = dim3(blocks, 1, 1);
        cfg.blockDim = dim3(THREADS, 1, 1);
        cfg.dynamicSmemBytes = 0;
        cfg.stream = 0;
        cudaLaunchAttribute attrs[1];
        attrs[0].id = cudaLaunchAttributeProgrammaticStreamSerialization;
        attrs[0].val.programmaticStreamSerializationAllowed = 1;
        cfg.attrs = attrs;
        cfg.numAttrs = 1;
        cudaLaunchKernelEx(&cfg, segsum_kernel,
                           (const float4*)feats, attn, seg, out,
                           (const float4*)bias, n_edges, n_nodes);
    }
}